// round 16
// baseline (speedup 1.0000x reference)
#include <cuda_runtime.h>
#include <cstdint>

#define N_NODES 1000000
#define N_EDGES 5000000

// Scratch (static device globals -- no allocation allowed).
// INVARIANT: g_S == 0 at every kernel_launch entry. First call: CUDA
// zero-initializes __device__ globals at module load. Every later call:
// k_node3 (last kernel of the previous launch) re-zeroes S after reading it,
// and stream ordering / gridSync serializes launches. Deterministic: every
// call performs identical work on identical state.
__device__ float g_dinv[N_NODES];
__device__ float g_xs[N_NODES];   // x * dinv   (layer-1 source values)
__device__ float g_ys[N_NODES];   // h2 * dinv  (layer-2 source values)
__device__ float g_S[N_NODES];    // edge-count, then scatter accumulator (reused)
__device__ int   g_is64;          // 1 if edge_index is int64 (written by k_deg blk 0)

// ---------------------------------------------------------------------------
// degree scatter: S[dst] += 1 (S starts at 0; self-loop folded into node1).
// 4 edges/thread @ TB=256 (measured best). Per-block dtype detection:
// int32 data misread as int64 yields values >= 2^32 with overwhelming prob;
// probes hit L2 after the first block.
__global__ void __launch_bounds__(256) k_deg(const void* __restrict__ ei) {
    __shared__ int s_is64;
    if (threadIdx.x == 0) s_is64 = 1;
    __syncthreads();
    if (threadIdx.x < 64) {
        long long v = ((const long long*)ei)[threadIdx.x];   // 512B: safe either dtype
        if (v < 0 || v >= (long long)N_NODES) s_is64 = 0;
    }
    __syncthreads();
    const int is64 = s_is64;
    if (blockIdx.x == 0 && threadIdx.x == 0) g_is64 = is64;  // publish for scatters
    cudaTriggerProgrammaticLaunchCompletion();   // node1 pre-sync touches only x
    cudaGridDependencySynchronize();             // prev launch done => S == 0
    unsigned t = blockIdx.x * blockDim.x + threadIdx.x;
    if (t >= N_EDGES / 4) return;                // 5M % 4 == 0
    unsigned base = t * 4u;
    int d[4];
    if (is64) {
        const longlong2* p = (const longlong2*)((const long long*)ei + N_EDGES) + (base >> 1);
        longlong2 a = __ldcs(p), b = __ldcs(p + 1);
        d[0]=(int)a.x; d[1]=(int)a.y; d[2]=(int)b.x; d[3]=(int)b.y;
    } else {
        int4 v = __ldcs((const int4*)((const int*)ei + N_EDGES + base));
        d[0]=v.x; d[1]=v.y; d[2]=v.z; d[3]=v.w;
    }
    #pragma unroll
    for (int k = 0; k < 4; k++) atomicAdd(&g_S[d[k]], 1.0f);
}

// ---------------------------------------------------------------------------
// node pass 1: dinv = rsqrt(S + 1) [self-loop], xs = x * dinv, S = 0.
// 8 nodes/thread. x preloaded pre-sync; trigger AFTER sync so successors'
// pre-sync reads of g_is64/ei are transitively ordered behind k_deg.
__global__ void k_node1(const float* __restrict__ x) {
    const unsigned H = N_NODES / 8;
    unsigned i = blockIdx.x * blockDim.x + threadIdx.x;
    float4 xv0, xv1;
    if (i < H) {
        xv0 = ((const float4*)x)[i];             // independent of k_deg
        xv1 = ((const float4*)x)[i + H];
    }
    cudaGridDependencySynchronize();             // k_deg atomics complete
    cudaTriggerProgrammaticLaunchCompletion();
    if (i >= H) return;
    float4 dg0 = ((const float4*)g_S)[i];
    float4 dg1 = ((const float4*)g_S)[i + H];
    float4 dv0, dv1;
    dv0.x = rsqrtf(dg0.x + 1.0f); dv0.y = rsqrtf(dg0.y + 1.0f);
    dv0.z = rsqrtf(dg0.z + 1.0f); dv0.w = rsqrtf(dg0.w + 1.0f);
    dv1.x = rsqrtf(dg1.x + 1.0f); dv1.y = rsqrtf(dg1.y + 1.0f);
    dv1.z = rsqrtf(dg1.z + 1.0f); dv1.w = rsqrtf(dg1.w + 1.0f);
    ((float4*)g_dinv)[i]     = dv0;
    ((float4*)g_dinv)[i + H] = dv1;
    ((float4*)g_xs)[i]     = make_float4(xv0.x*dv0.x, xv0.y*dv0.y, xv0.z*dv0.z, xv0.w*dv0.w);
    ((float4*)g_xs)[i + H] = make_float4(xv1.x*dv1.x, xv1.y*dv1.y, xv1.z*dv1.z, xv1.w*dv1.w);
    float4 zero = make_float4(0.f, 0.f, 0.f, 0.f);
    ((float4*)g_S)[i]     = zero;
    ((float4*)g_S)[i + H] = zero;
}

// ---------------------------------------------------------------------------
// edge scatter: S[dst] += vals[src].  2 edges/thread + TB=128: the certified
// optimum (e/t U-curve: 8->49.4, 4->46.3, 2->44.9, 1->48.8;
//          TB  U-curve: 256->44.86, 128->44.51, 64->46.88 us).
template <int WHICH>   // 0: vals = g_xs, 1: vals = g_ys
__global__ void __launch_bounds__(128) k_scatter(const void* __restrict__ ei) {
    cudaTriggerProgrammaticLaunchCompletion();
    unsigned t = blockIdx.x * blockDim.x + threadIdx.x;
    const bool active = t < (N_EDGES / 2);       // 5M % 2 == 0
    unsigned base = t * 2u;
    int s[2], d[2];
    if (active) {
        if (g_is64) {                            // stable: k_deg transitively done
            longlong2 sv = __ldcs((const longlong2*)((const long long*)ei) + t);
            longlong2 dv = __ldcs((const longlong2*)((const long long*)ei + N_EDGES) + t);
            s[0]=(int)sv.x; s[1]=(int)sv.y;
            d[0]=(int)dv.x; d[1]=(int)dv.y;
        } else {
            int2 sv = __ldcs((const int2*)((const int*)ei + base));
            int2 dv = __ldcs((const int2*)((const int*)ei + N_EDGES + base));
            s[0]=sv.x; s[1]=sv.y;
            d[0]=dv.x; d[1]=dv.y;
        }
    }
    cudaGridDependencySynchronize();             // predecessor node pass complete
    if (!active) return;
    const float* vals = WHICH ? g_ys : g_xs;
    float v0 = __ldg(&vals[s[0]]);
    float v1 = __ldg(&vals[s[1]]);
    atomicAdd(&g_S[d[0]], v0);
    atomicAdd(&g_S[d[1]], v1);
}

// ---------------------------------------------------------------------------
// node pass 2: agg1 -> relu/W2 fold -> ys; re-zero S.  8 nodes/thread.
// Weights live in SHARED memory (48 floats, broadcast LDS) instead of
// 48 registers: regs 71 -> ~30, occupancy 31% -> ~full, fixing the
// latency-limited profile (9.6us @ 1.25TB/s).
__global__ void __launch_bounds__(256) k_node2(const float* __restrict__ W1,
                                               const float* __restrict__ b1,
                                               const float* __restrict__ W2) {
    __shared__ float sw1[16], sbb[16], sw2[16];
    if (threadIdx.x < 16) {                      // external inputs: pre-sync OK
        sw1[threadIdx.x] = W1[threadIdx.x];
        sbb[threadIdx.x] = b1[threadIdx.x];
        sw2[threadIdx.x] = W2[threadIdx.x];
    }
    __syncthreads();
    cudaGridDependencySynchronize();             // scatter<0> atomics complete
    cudaTriggerProgrammaticLaunchCompletion();
    const unsigned H = N_NODES / 8;
    unsigned i = blockIdx.x * blockDim.x + threadIdx.x;
    if (i >= H) return;

    float4 S0  = ((const float4*)g_S)[i];
    float4 S1  = ((const float4*)g_S)[i + H];
    float4 xs0 = ((const float4*)g_xs)[i];
    float4 xs1 = ((const float4*)g_xs)[i + H];
    float4 d0  = ((const float4*)g_dinv)[i];
    float4 d1  = ((const float4*)g_dinv)[i + H];

    float agg[8] = { d0.x*(S0.x+xs0.x), d0.y*(S0.y+xs0.y),
                     d0.z*(S0.z+xs0.z), d0.w*(S0.w+xs0.w),
                     d1.x*(S1.x+xs1.x), d1.y*(S1.y+xs1.y),
                     d1.z*(S1.z+xs1.z), d1.w*(S1.w+xs1.w) };
    float h2[8] = {0.f,0.f,0.f,0.f,0.f,0.f,0.f,0.f};
    #pragma unroll
    for (int f = 0; f < 16; f++) {
        float w1f = sw1[f], bf = sbb[f], w2f = sw2[f];
        #pragma unroll
        for (int j = 0; j < 8; j++)
            h2[j] += fmaxf(fmaf(agg[j], w1f, bf), 0.0f) * w2f;
    }
    ((float4*)g_ys)[i]     = make_float4(h2[0]*d0.x, h2[1]*d0.y, h2[2]*d0.z, h2[3]*d0.w);
    ((float4*)g_ys)[i + H] = make_float4(h2[4]*d1.x, h2[5]*d1.y, h2[6]*d1.z, h2[7]*d1.w);
    float4 zero = make_float4(0.f, 0.f, 0.f, 0.f);
    ((float4*)g_S)[i]     = zero;
    ((float4*)g_S)[i + H] = zero;
}

// ---------------------------------------------------------------------------
// node pass 3: out = dinv*(S + ys) + b2, then S = 0 (restores the launch
// invariant so the next replay's k_deg starts from a clean accumulator).
__global__ void k_node3(float* __restrict__ out, const float* __restrict__ b2) {
    float bias = b2[0];                          // external input, pre-sync
    cudaGridDependencySynchronize();             // scatter<1> atomics complete
    const unsigned H = N_NODES / 8;
    unsigned i = blockIdx.x * blockDim.x + threadIdx.x;
    if (i >= H) return;
    float4 S0 = ((const float4*)g_S)[i];
    float4 S1 = ((const float4*)g_S)[i + H];
    float4 y0 = ((const float4*)g_ys)[i];
    float4 y1 = ((const float4*)g_ys)[i + H];
    float4 d0 = ((const float4*)g_dinv)[i];
    float4 d1 = ((const float4*)g_dinv)[i + H];
    ((float4*)out)[i] = make_float4(fmaf(d0.x, S0.x + y0.x, bias),
                                    fmaf(d0.y, S0.y + y0.y, bias),
                                    fmaf(d0.z, S0.z + y0.z, bias),
                                    fmaf(d0.w, S0.w + y0.w, bias));
    ((float4*)out)[i + H] = make_float4(fmaf(d1.x, S1.x + y1.x, bias),
                                        fmaf(d1.y, S1.y + y1.y, bias),
                                        fmaf(d1.z, S1.z + y1.z, bias),
                                        fmaf(d1.w, S1.w + y1.w, bias));
    float4 zero = make_float4(0.f, 0.f, 0.f, 0.f);
    ((float4*)g_S)[i]     = zero;
    ((float4*)g_S)[i + H] = zero;
}

// ---------------------------------------------------------------------------
template <typename... Args>
static void launch_pdl(void (*kern)(Args...), int grid, int block, Args... args) {
    cudaLaunchConfig_t cfg = {};
    cfg.gridDim  = dim3(grid, 1, 1);
    cfg.blockDim = dim3(block, 1, 1);
    cfg.stream   = 0;
    cudaLaunchAttribute attr[1];
    attr[0].id = cudaLaunchAttributeProgrammaticStreamSerialization;
    attr[0].val.programmaticStreamSerializationAllowed = 1;
    cfg.attrs = attr;
    cfg.numAttrs = 1;
    cudaLaunchKernelEx(&cfg, kern, args...);
}

extern "C" void kernel_launch(void* const* d_in, const int* in_sizes, int n_in,
                              void* d_out, int out_size) {
    const float* x  = (const float*)d_in[0];
    const void*  ei = d_in[1];
    const float* W1 = (const float*)d_in[2];
    const float* b1 = (const float*)d_in[3];
    const float* W2 = (const float*)d_in[4];
    const float* b2 = (const float*)d_in[5];
    float* out = (float*)d_out;

    const int TB = 256;
    const int node8Blocks = (N_NODES / 8 + TB - 1) / TB;   // 489
    const int deg4Blocks  = (N_EDGES / 4 + TB - 1) / TB;   // 4883 (TB=256)
    const int sc2Blocks   = (N_EDGES / 2 + 127) / 128;     // 19532 (TB=128)

    launch_pdl(k_deg,        deg4Blocks,  TB,  ei);
    launch_pdl(k_node1,      node8Blocks, TB,  x);
    launch_pdl(k_scatter<0>, sc2Blocks,   128, ei);
    launch_pdl(k_node2,      node8Blocks, TB,  W1, b1, W2);
    launch_pdl(k_scatter<1>, sc2Blocks,   128, ei);
    launch_pdl(k_node3,      node8Blocks, TB,  out, b2);
}

// round 17
// speedup vs baseline: 1.0055x; 1.0055x over previous
#include <cuda_runtime.h>
#include <cstdint>

#define N_NODES 1000000
#define N_EDGES 5000000

// Scratch (static device globals -- no allocation allowed).
// INVARIANT: g_S == 0 at every kernel_launch entry. First call: CUDA
// zero-initializes __device__ globals at module load. Every later call:
// k_node3 (last kernel of the previous launch) re-zeroes S after reading it,
// and stream ordering / gridSync serializes launches. Deterministic: every
// call performs identical work on identical state.
__device__ float g_dinv[N_NODES];
__device__ float g_xs[N_NODES];   // x * dinv   (layer-1 source values)
__device__ float g_ys[N_NODES];   // h2 * dinv  (layer-2 source values)
__device__ float g_S[N_NODES];    // edge-count, then scatter accumulator (reused)
__device__ int   g_is64;          // 1 if edge_index is int64 (written by k_deg blk 0)

// ---------------------------------------------------------------------------
// degree scatter: S[dst] += 1 (S starts at 0; self-loop folded into node1).
// 4 edges/thread @ TB=256 (measured best). Per-block dtype detection:
// int32 data misread as int64 yields values >= 2^32 with overwhelming prob;
// probes hit L2 after the first block.
__global__ void __launch_bounds__(256) k_deg(const void* __restrict__ ei) {
    __shared__ int s_is64;
    if (threadIdx.x == 0) s_is64 = 1;
    __syncthreads();
    if (threadIdx.x < 64) {
        long long v = ((const long long*)ei)[threadIdx.x];   // 512B: safe either dtype
        if (v < 0 || v >= (long long)N_NODES) s_is64 = 0;
    }
    __syncthreads();
    const int is64 = s_is64;
    if (blockIdx.x == 0 && threadIdx.x == 0) g_is64 = is64;  // publish for scatters
    cudaTriggerProgrammaticLaunchCompletion();   // node1 pre-sync touches only x
    cudaGridDependencySynchronize();             // prev launch done => S == 0
    unsigned t = blockIdx.x * blockDim.x + threadIdx.x;
    if (t >= N_EDGES / 4) return;                // 5M % 4 == 0
    unsigned base = t * 4u;
    int d[4];
    if (is64) {
        const longlong2* p = (const longlong2*)((const long long*)ei + N_EDGES) + (base >> 1);
        longlong2 a = __ldcs(p), b = __ldcs(p + 1);
        d[0]=(int)a.x; d[1]=(int)a.y; d[2]=(int)b.x; d[3]=(int)b.y;
    } else {
        int4 v = __ldcs((const int4*)((const int*)ei + N_EDGES + base));
        d[0]=v.x; d[1]=v.y; d[2]=v.z; d[3]=v.w;
    }
    #pragma unroll
    for (int k = 0; k < 4; k++) atomicAdd(&g_S[d[k]], 1.0f);
}

// ---------------------------------------------------------------------------
// node pass 1: dinv = rsqrt(S + 1) [self-loop], xs = x * dinv, S = 0.
// 8 nodes/thread. x preloaded pre-sync; trigger AFTER sync so successors'
// pre-sync reads of g_is64/ei are transitively ordered behind k_deg.
__global__ void k_node1(const float* __restrict__ x) {
    const unsigned H = N_NODES / 8;
    unsigned i = blockIdx.x * blockDim.x + threadIdx.x;
    float4 xv0, xv1;
    if (i < H) {
        xv0 = ((const float4*)x)[i];             // independent of k_deg
        xv1 = ((const float4*)x)[i + H];
    }
    cudaGridDependencySynchronize();             // k_deg atomics complete
    cudaTriggerProgrammaticLaunchCompletion();
    if (i >= H) return;
    float4 dg0 = ((const float4*)g_S)[i];
    float4 dg1 = ((const float4*)g_S)[i + H];
    float4 dv0, dv1;
    dv0.x = rsqrtf(dg0.x + 1.0f); dv0.y = rsqrtf(dg0.y + 1.0f);
    dv0.z = rsqrtf(dg0.z + 1.0f); dv0.w = rsqrtf(dg0.w + 1.0f);
    dv1.x = rsqrtf(dg1.x + 1.0f); dv1.y = rsqrtf(dg1.y + 1.0f);
    dv1.z = rsqrtf(dg1.z + 1.0f); dv1.w = rsqrtf(dg1.w + 1.0f);
    ((float4*)g_dinv)[i]     = dv0;
    ((float4*)g_dinv)[i + H] = dv1;
    ((float4*)g_xs)[i]     = make_float4(xv0.x*dv0.x, xv0.y*dv0.y, xv0.z*dv0.z, xv0.w*dv0.w);
    ((float4*)g_xs)[i + H] = make_float4(xv1.x*dv1.x, xv1.y*dv1.y, xv1.z*dv1.z, xv1.w*dv1.w);
    float4 zero = make_float4(0.f, 0.f, 0.f, 0.f);
    ((float4*)g_S)[i]     = zero;
    ((float4*)g_S)[i + H] = zero;
}

// ---------------------------------------------------------------------------
// edge scatter: S[dst] += vals[src].  2 edges/thread + TB=128: the certified
// optimum (e/t U-curve: 8->49.4, 4->46.3, 2->44.9, 1->48.8;
//          TB  U-curve: 256->44.86, 128->44.51, 64->46.88 us).
template <int WHICH>   // 0: vals = g_xs, 1: vals = g_ys
__global__ void __launch_bounds__(128) k_scatter(const void* __restrict__ ei) {
    cudaTriggerProgrammaticLaunchCompletion();
    unsigned t = blockIdx.x * blockDim.x + threadIdx.x;
    const bool active = t < (N_EDGES / 2);       // 5M % 2 == 0
    unsigned base = t * 2u;
    int s[2], d[2];
    if (active) {
        if (g_is64) {                            // stable: k_deg transitively done
            longlong2 sv = __ldcs((const longlong2*)((const long long*)ei) + t);
            longlong2 dv = __ldcs((const longlong2*)((const long long*)ei + N_EDGES) + t);
            s[0]=(int)sv.x; s[1]=(int)sv.y;
            d[0]=(int)dv.x; d[1]=(int)dv.y;
        } else {
            int2 sv = __ldcs((const int2*)((const int*)ei + base));
            int2 dv = __ldcs((const int2*)((const int*)ei + N_EDGES + base));
            s[0]=sv.x; s[1]=sv.y;
            d[0]=dv.x; d[1]=dv.y;
        }
    }
    cudaGridDependencySynchronize();             // predecessor node pass complete
    if (!active) return;
    const float* vals = WHICH ? g_ys : g_xs;
    float v0 = __ldg(&vals[s[0]]);
    float v1 = __ldg(&vals[s[1]]);
    atomicAdd(&g_S[d[0]], v0);
    atomicAdd(&g_S[d[1]], v1);
}

// ---------------------------------------------------------------------------
// node pass 2: agg1 -> relu/W2 fold -> ys; re-zero S.  4 nodes/thread +
// smem weights: regs ~32 (reg ceiling lifted) AND 977-block grid (grid
// ceiling lifted -- the 8/thread variant's 489 blocks capped occ at 41%).
__global__ void __launch_bounds__(256) k_node2(const float* __restrict__ W1,
                                               const float* __restrict__ b1,
                                               const float* __restrict__ W2) {
    __shared__ float sw1[16], sbb[16], sw2[16];
    if (threadIdx.x < 16) {                      // external inputs: pre-sync OK
        sw1[threadIdx.x] = W1[threadIdx.x];
        sbb[threadIdx.x] = b1[threadIdx.x];
        sw2[threadIdx.x] = W2[threadIdx.x];
    }
    __syncthreads();
    cudaGridDependencySynchronize();             // scatter<0> atomics complete
    cudaTriggerProgrammaticLaunchCompletion();
    unsigned i = blockIdx.x * blockDim.x + threadIdx.x;
    if (i >= N_NODES / 4) return;

    float4 Sv  = ((const float4*)g_S)[i];
    float4 xsv = ((const float4*)g_xs)[i];
    float4 dv  = ((const float4*)g_dinv)[i];

    float agg[4] = { dv.x*(Sv.x+xsv.x), dv.y*(Sv.y+xsv.y),
                     dv.z*(Sv.z+xsv.z), dv.w*(Sv.w+xsv.w) };
    float h2[4] = {0.f, 0.f, 0.f, 0.f};
    #pragma unroll
    for (int f = 0; f < 16; f++) {
        float w1f = sw1[f], bf = sbb[f], w2f = sw2[f];
        #pragma unroll
        for (int j = 0; j < 4; j++)
            h2[j] += fmaxf(fmaf(agg[j], w1f, bf), 0.0f) * w2f;
    }
    ((float4*)g_ys)[i] = make_float4(h2[0]*dv.x, h2[1]*dv.y, h2[2]*dv.z, h2[3]*dv.w);
    ((float4*)g_S)[i]  = make_float4(0.f, 0.f, 0.f, 0.f);
}

// ---------------------------------------------------------------------------
// node pass 3: out = dinv*(S + ys) + b2, then S = 0 (restores the launch
// invariant so the next replay's k_deg starts from a clean accumulator).
__global__ void k_node3(float* __restrict__ out, const float* __restrict__ b2) {
    float bias = b2[0];                          // external input, pre-sync
    cudaGridDependencySynchronize();             // scatter<1> atomics complete
    const unsigned H = N_NODES / 8;
    unsigned i = blockIdx.x * blockDim.x + threadIdx.x;
    if (i >= H) return;
    float4 S0 = ((const float4*)g_S)[i];
    float4 S1 = ((const float4*)g_S)[i + H];
    float4 y0 = ((const float4*)g_ys)[i];
    float4 y1 = ((const float4*)g_ys)[i + H];
    float4 d0 = ((const float4*)g_dinv)[i];
    float4 d1 = ((const float4*)g_dinv)[i + H];
    ((float4*)out)[i] = make_float4(fmaf(d0.x, S0.x + y0.x, bias),
                                    fmaf(d0.y, S0.y + y0.y, bias),
                                    fmaf(d0.z, S0.z + y0.z, bias),
                                    fmaf(d0.w, S0.w + y0.w, bias));
    ((float4*)out)[i + H] = make_float4(fmaf(d1.x, S1.x + y1.x, bias),
                                        fmaf(d1.y, S1.y + y1.y, bias),
                                        fmaf(d1.z, S1.z + y1.z, bias),
                                        fmaf(d1.w, S1.w + y1.w, bias));
    float4 zero = make_float4(0.f, 0.f, 0.f, 0.f);
    ((float4*)g_S)[i]     = zero;
    ((float4*)g_S)[i + H] = zero;
}

// ---------------------------------------------------------------------------
template <typename... Args>
static void launch_pdl(void (*kern)(Args...), int grid, int block, Args... args) {
    cudaLaunchConfig_t cfg = {};
    cfg.gridDim  = dim3(grid, 1, 1);
    cfg.blockDim = dim3(block, 1, 1);
    cfg.stream   = 0;
    cudaLaunchAttribute attr[1];
    attr[0].id = cudaLaunchAttributeProgrammaticStreamSerialization;
    attr[0].val.programmaticStreamSerializationAllowed = 1;
    cfg.attrs = attr;
    cfg.numAttrs = 1;
    cudaLaunchKernelEx(&cfg, kern, args...);
}

extern "C" void kernel_launch(void* const* d_in, const int* in_sizes, int n_in,
                              void* d_out, int out_size) {
    const float* x  = (const float*)d_in[0];
    const void*  ei = d_in[1];
    const float* W1 = (const float*)d_in[2];
    const float* b1 = (const float*)d_in[3];
    const float* W2 = (const float*)d_in[4];
    const float* b2 = (const float*)d_in[5];
    float* out = (float*)d_out;

    const int TB = 256;
    const int node8Blocks = (N_NODES / 8 + TB - 1) / TB;   // 489
    const int node4Blocks = (N_NODES / 4 + TB - 1) / TB;   // 977
    const int deg4Blocks  = (N_EDGES / 4 + TB - 1) / TB;   // 4883 (TB=256)
    const int sc2Blocks   = (N_EDGES / 2 + 127) / 128;     // 19532 (TB=128)

    launch_pdl(k_deg,        deg4Blocks,  TB,  ei);
    launch_pdl(k_node1,      node8Blocks, TB,  x);
    launch_pdl(k_scatter<0>, sc2Blocks,   128, ei);
    launch_pdl(k_node2,      node4Blocks, TB,  W1, b1, W2);
    launch_pdl(k_scatter<1>, sc2Blocks,   128, ei);
    launch_pdl(k_node3,      node8Blocks, TB,  out, b2);
}